// round 5
// baseline (speedup 1.0000x reference)
#include <cuda_runtime.h>
#include <cuda_bf16.h>

// LightGCNConv R5: self-cleaning binned gather, int4 bucket loads, 32-bit idx.
//
// Pipeline (3 launches):
//  1) bin:  outdeg atomics; slot=atomicAdd(cursor[dst]); bucket[dst*CAP+slot]=src
//           (int4-vectorized edge reads; overflow -> pair list)
//  2) norm: nsrc=rsqrt(max(outdeg,1)), ndst=rsqrt(max(cursor,1));
//           zeroes outdeg; snapshots+zeroes ovf_count   [self-clean]
//  3) gather: 16 lanes/node, int4 bucket index loads, reg accumulate,
//           one write per output element; lane0 zeroes cursor [self-clean]
//
// All __device__ state returns to zero after each launch -> graph replays are
// deterministic; statics are zero-initialized for the first call.

#define MAX_NODES 100000
#define DFEAT 64
#define DVEC 16  // float4s per row
#define CAP 64   // bucket capacity (avg in-deg 10; Poisson tail << 64)
#define OVF_MAX 4096

__device__ int   g_outdeg[MAX_NODES];
__device__ int   g_cursor[MAX_NODES];          // becomes in-degree
__device__ float g_nsrc[MAX_NODES];
__device__ float g_ndst[MAX_NODES];
__device__ int   g_bucket[MAX_NODES * CAP];    // 25.6 MB scratch
__device__ int   g_ovf_src[OVF_MAX];
__device__ int   g_ovf_dst[OVF_MAX];
__device__ int   g_ovf_count;                  // raw counter (bin)
__device__ int   g_ovf_n;                      // snapshot used by gather

__device__ __forceinline__ void bin_one(int s, int d) {
    atomicAdd(&g_outdeg[s], 1);
    int slot = atomicAdd(&g_cursor[d], 1);
    if (slot < CAP) {
        g_bucket[d * CAP + slot] = s;
    } else {
        int pos = atomicAdd(&g_ovf_count, 1);
        if (pos < OVF_MAX) {
            g_ovf_src[pos] = s;
            g_ovf_dst[pos] = d;
        }
    }
}

// 4 edges per thread via int4 loads.
__global__ void bin_kernel(const int4* __restrict__ src4,
                           const int4* __restrict__ dst4,
                           const int* __restrict__ src,
                           const int* __restrict__ dst,
                           int E4, int E) {
    int t = blockIdx.x * blockDim.x + threadIdx.x;
    if (t < E4) {
        int4 s = __ldg(&src4[t]);
        int4 d = __ldg(&dst4[t]);
        bin_one(s.x, d.x);
        bin_one(s.y, d.y);
        bin_one(s.z, d.z);
        bin_one(s.w, d.w);
    } else {
        // tail edges (E % 4)
        int e = E4 * 4 + (t - E4);
        if (e < E) bin_one(src[e], dst[e]);
    }
}

__global__ void norm_kernel(int n) {
    int i = blockIdx.x * blockDim.x + threadIdx.x;
    if (i < n) {
        g_nsrc[i] = rsqrtf((float)max(g_outdeg[i], 1));
        g_ndst[i] = rsqrtf((float)max(g_cursor[i], 1));
        g_outdeg[i] = 0;                       // self-clean for next replay
    }
    if (i == 0) {
        g_ovf_n = min(g_ovf_count, OVF_MAX);   // snapshot for gather
        g_ovf_count = 0;                       // self-clean
    }
}

// 16 lanes per node; lane q owns float4 #q. No atomics, one write per elem.
__global__ void gather_kernel(const float4* __restrict__ feat,
                              float4* __restrict__ out, int N) {
    unsigned t = blockIdx.x * blockDim.x + threadIdx.x;
    unsigned node = t >> 4;
    unsigned q = t & 15u;
    if (node >= (unsigned)N) return;

    int deg = __ldg(&g_cursor[node]);          // broadcast across 16 lanes
    if (q == 0) g_cursor[node] = 0;            // self-clean for next replay
    int k = min(deg, CAP);

    float4 acc = make_float4(0.f, 0.f, 0.f, 0.f);
    const int* bkt = &g_bucket[node * CAP];    // 256B-aligned

    int i = 0;
    for (; i + 4 <= k; i += 4) {
        int4 s4 = __ldg((const int4*)&bkt[i]); // 1 broadcast LDG per 4 edges
        float4 v0 = __ldg(&feat[(unsigned)s4.x * DVEC + q]);
        float4 v1 = __ldg(&feat[(unsigned)s4.y * DVEC + q]);
        float4 v2 = __ldg(&feat[(unsigned)s4.z * DVEC + q]);
        float4 v3 = __ldg(&feat[(unsigned)s4.w * DVEC + q]);
        float r0 = __ldg(&g_nsrc[s4.x]);
        float r1 = __ldg(&g_nsrc[s4.y]);
        float r2 = __ldg(&g_nsrc[s4.z]);
        float r3 = __ldg(&g_nsrc[s4.w]);
        acc.x = fmaf(v0.x, r0, acc.x); acc.y = fmaf(v0.y, r0, acc.y);
        acc.z = fmaf(v0.z, r0, acc.z); acc.w = fmaf(v0.w, r0, acc.w);
        acc.x = fmaf(v1.x, r1, acc.x); acc.y = fmaf(v1.y, r1, acc.y);
        acc.z = fmaf(v1.z, r1, acc.z); acc.w = fmaf(v1.w, r1, acc.w);
        acc.x = fmaf(v2.x, r2, acc.x); acc.y = fmaf(v2.y, r2, acc.y);
        acc.z = fmaf(v2.z, r2, acc.z); acc.w = fmaf(v2.w, r2, acc.w);
        acc.x = fmaf(v3.x, r3, acc.x); acc.y = fmaf(v3.y, r3, acc.y);
        acc.z = fmaf(v3.z, r3, acc.z); acc.w = fmaf(v3.w, r3, acc.w);
    }
    for (; i < k; i++) {
        int s = __ldg(&bkt[i]);
        float rn = __ldg(&g_nsrc[s]);
        float4 v = __ldg(&feat[(unsigned)s * DVEC + q]);
        acc.x = fmaf(v.x, rn, acc.x); acc.y = fmaf(v.y, rn, acc.y);
        acc.z = fmaf(v.z, rn, acc.z); acc.w = fmaf(v.w, rn, acc.w);
    }

    // Slow path: edges that overflowed this node's bucket (expected: none).
    if (deg > CAP) {
        int ovfn = g_ovf_n;
        for (int j = 0; j < ovfn; j++) {
            if (g_ovf_dst[j] == (int)node) {
                int s = g_ovf_src[j];
                float rn = __ldg(&g_nsrc[s]);
                float4 v = __ldg(&feat[(unsigned)s * DVEC + q]);
                acc.x = fmaf(v.x, rn, acc.x); acc.y = fmaf(v.y, rn, acc.y);
                acc.z = fmaf(v.z, rn, acc.z); acc.w = fmaf(v.w, rn, acc.w);
            }
        }
    }

    float nd = __ldg(&g_ndst[node]);
    acc.x *= nd; acc.y *= nd; acc.z *= nd; acc.w *= nd;
    out[node * DVEC + q] = acc;
}

extern "C" void kernel_launch(void* const* d_in, const int* in_sizes, int n_in,
                              void* d_out, int out_size) {
    const float4* feat = (const float4*)d_in[0];
    const int*    src  = (const int*)d_in[1];
    const int*    dst  = (const int*)d_in[2];
    float4*       out  = (float4*)d_out;

    int N = in_sizes[0] / DFEAT;   // 100000
    int E = in_sizes[1];           // 1000000

    // 1) degree count + dst binning (4 edges/thread + tail threads)
    {
        int E4 = E / 4;
        int tail = E - E4 * 4;
        int total = E4 + tail;
        int threads = 256;
        int blocks = (total + threads - 1) / threads;
        bin_kernel<<<blocks, threads>>>((const int4*)src, (const int4*)dst,
                                        src, dst, E4, E);
    }

    // 2) per-node norms (+ self-clean outdeg / ovf_count)
    {
        int threads = 256;
        int blocks = (N + threads - 1) / threads;
        norm_kernel<<<blocks, threads>>>(N);
    }

    // 3) register-accumulated gather (+ self-clean cursor)
    {
        long long total = (long long)N * DVEC;
        int threads = 256;
        int blocks = (int)((total + threads - 1) / threads);
        gather_kernel<<<blocks, threads>>>(feat, out, N);
    }
}

// round 6
// speedup vs baseline: 1.0451x; 1.0451x over previous
#include <cuda_runtime.h>
#include <cuda_bf16.h>

// LightGCNConv R6: R4's proven kernel shapes + self-cleaning state (3 launches).
//
//  1) bin:  one edge/thread; outdeg atomics; slot=atomicAdd(cursor[dst]);
//           bucket[dst*CAP+slot]=src; overflow -> pair list
//  2) norm: nsrc/ndst rsqrt; zeroes outdeg, snapshots+zeroes ovf_count
//  3) gather: 16 lanes/node, reg accumulate, one write per output element;
//           lane0 zeroes cursor
//
// All __device__ state returns to zero after each graph replay.

#define MAX_NODES 100000
#define DFEAT 64
#define DVEC 16  // float4s per row
#define CAP 64   // bucket capacity (avg in-deg 10; Poisson tail << 64)
#define OVF_MAX 4096

__device__ int   g_outdeg[MAX_NODES];
__device__ int   g_cursor[MAX_NODES];          // becomes in-degree
__device__ float g_nsrc[MAX_NODES];
__device__ float g_ndst[MAX_NODES];
__device__ int   g_bucket[MAX_NODES * CAP];    // 25.6 MB scratch
__device__ int   g_ovf_src[OVF_MAX];
__device__ int   g_ovf_dst[OVF_MAX];
__device__ int   g_ovf_count;                  // raw counter (bin)
__device__ int   g_ovf_n;                      // snapshot used by gather

__global__ void bin_kernel(const int* __restrict__ src,
                           const int* __restrict__ dst, int E) {
    int e = blockIdx.x * blockDim.x + threadIdx.x;
    if (e >= E) return;
    int s = src[e];
    int d = dst[e];
    atomicAdd(&g_outdeg[s], 1);
    int slot = atomicAdd(&g_cursor[d], 1);
    if (slot < CAP) {
        g_bucket[d * CAP + slot] = s;
    } else {
        int pos = atomicAdd(&g_ovf_count, 1);
        if (pos < OVF_MAX) {
            g_ovf_src[pos] = s;
            g_ovf_dst[pos] = d;
        }
    }
}

__global__ void norm_kernel(int n) {
    int i = blockIdx.x * blockDim.x + threadIdx.x;
    if (i < n) {
        g_nsrc[i] = rsqrtf((float)max(g_outdeg[i], 1));
        g_ndst[i] = rsqrtf((float)max(g_cursor[i], 1));
        g_outdeg[i] = 0;                       // self-clean for next replay
    }
    if (i == 0) {
        g_ovf_n = min(g_ovf_count, OVF_MAX);   // snapshot for gather
        g_ovf_count = 0;                       // self-clean
    }
}

// 16 lanes per node; lane q owns float4 #q. No atomics, one write per elem.
__global__ void gather_kernel(const float4* __restrict__ feat,
                              float4* __restrict__ out, int N) {
    unsigned t = blockIdx.x * blockDim.x + threadIdx.x;
    unsigned node = t >> 4;
    unsigned q = t & 15u;
    if (node >= (unsigned)N) return;

    int deg = __ldg(&g_cursor[node]);          // broadcast across the 16 lanes
    if (q == 0) g_cursor[node] = 0;            // self-clean for next replay
    int k = min(deg, CAP);

    float4 acc = make_float4(0.f, 0.f, 0.f, 0.f);
    const int* bkt = &g_bucket[node * CAP];

    #pragma unroll 4
    for (int i = 0; i < k; i++) {
        int s = __ldg(&bkt[i]);                // broadcast
        float rn = __ldg(&g_nsrc[s]);          // broadcast
        float4 v = __ldg(&feat[(unsigned)s * DVEC + q]);
        acc.x = fmaf(v.x, rn, acc.x);
        acc.y = fmaf(v.y, rn, acc.y);
        acc.z = fmaf(v.z, rn, acc.z);
        acc.w = fmaf(v.w, rn, acc.w);
    }

    // Slow path: edges that overflowed this node's bucket (expected: none).
    if (deg > CAP) {
        int ovfn = g_ovf_n;
        for (int j = 0; j < ovfn; j++) {
            if (g_ovf_dst[j] == (int)node) {
                int s = g_ovf_src[j];
                float rn = __ldg(&g_nsrc[s]);
                float4 v = __ldg(&feat[(unsigned)s * DVEC + q]);
                acc.x = fmaf(v.x, rn, acc.x);
                acc.y = fmaf(v.y, rn, acc.y);
                acc.z = fmaf(v.z, rn, acc.z);
                acc.w = fmaf(v.w, rn, acc.w);
            }
        }
    }

    float nd = __ldg(&g_ndst[node]);
    acc.x *= nd; acc.y *= nd; acc.z *= nd; acc.w *= nd;
    out[node * DVEC + q] = acc;
}

extern "C" void kernel_launch(void* const* d_in, const int* in_sizes, int n_in,
                              void* d_out, int out_size) {
    const float4* feat = (const float4*)d_in[0];
    const int*    src  = (const int*)d_in[1];
    const int*    dst  = (const int*)d_in[2];
    float4*       out  = (float4*)d_out;

    int N = in_sizes[0] / DFEAT;   // 100000
    int E = in_sizes[1];           // 1000000

    // 1) degree count + dst binning (one edge per thread)
    {
        int threads = 256;
        int blocks = (E + threads - 1) / threads;
        bin_kernel<<<blocks, threads>>>(src, dst, E);
    }

    // 2) per-node norms (+ self-clean outdeg / ovf_count)
    {
        int threads = 256;
        int blocks = (N + threads - 1) / threads;
        norm_kernel<<<blocks, threads>>>(N);
    }

    // 3) register-accumulated gather (+ self-clean cursor)
    {
        long long total = (long long)N * DVEC;
        int threads = 256;
        int blocks = (int)((total + threads - 1) / threads);
        gather_kernel<<<blocks, threads>>>(feat, out, N);
    }
}

// round 7
// speedup vs baseline: 1.8277x; 1.7488x over previous
#include <cuda_runtime.h>
#include <cuda_bf16.h>

// LightGCNConv R7: exact R4 pipeline (measured 48.3us) with CAP=32 so each
// node's bucket row is exactly one 128B cache line.
//
// Pipeline (4 launches, no memset):
//  1) zero: outdeg/cursor/ovf_count = 0
//  2) bin: one edge/thread; outdeg RED; slot=atomicAdd(cursor[dst]);
//     bucket[dst*CAP+slot]=src; overflow (deg>CAP, ~never) -> pair list
//  3) norm: nsrc=rsqrt(max(outdeg,1)), ndst=rsqrt(max(cursor,1))
//  4) gather: 16 lanes/node, reg accumulate, one write per output element

#define MAX_NODES 100000
#define DFEAT 64
#define DVEC 16  // float4s per row
#define CAP 32   // bucket row = 128B = one cache line; P(deg>32) ~ 4e-9
#define OVF_MAX 4096

__device__ int   g_outdeg[MAX_NODES];
__device__ int   g_cursor[MAX_NODES];          // becomes in-degree
__device__ float g_nsrc[MAX_NODES];
__device__ float g_ndst[MAX_NODES];
__device__ int   g_bucket[MAX_NODES * CAP];    // 12.8 MB scratch
__device__ int   g_ovf_src[OVF_MAX];
__device__ int   g_ovf_dst[OVF_MAX];
__device__ int   g_ovf_count;

__global__ void zero_kernel(int n) {
    int i = blockIdx.x * blockDim.x + threadIdx.x;
    if (i < n) {
        g_outdeg[i] = 0;
        g_cursor[i] = 0;
    }
    if (i == 0) g_ovf_count = 0;
}

__global__ void bin_kernel(const int* __restrict__ src,
                           const int* __restrict__ dst, int E) {
    int e = blockIdx.x * blockDim.x + threadIdx.x;
    if (e >= E) return;
    int s = src[e];
    int d = dst[e];
    atomicAdd(&g_outdeg[s], 1);                // result unused -> RED
    int slot = atomicAdd(&g_cursor[d], 1);
    if (slot < CAP) {
        g_bucket[d * CAP + slot] = s;
    } else {
        int pos = atomicAdd(&g_ovf_count, 1);
        if (pos < OVF_MAX) {
            g_ovf_src[pos] = s;
            g_ovf_dst[pos] = d;
        }
    }
}

__global__ void norm_kernel(int n) {
    int i = blockIdx.x * blockDim.x + threadIdx.x;
    if (i < n) {
        g_nsrc[i] = rsqrtf((float)max(g_outdeg[i], 1));
        g_ndst[i] = rsqrtf((float)max(g_cursor[i], 1));
    }
}

// 16 lanes per node; lane q owns float4 #q. No atomics, one write per elem.
__global__ void gather_kernel(const float4* __restrict__ feat,
                              float4* __restrict__ out, int N) {
    int t = blockIdx.x * blockDim.x + threadIdx.x;
    int node = t >> 4;
    int q = t & 15;
    if (node >= N) return;

    int deg = __ldg(&g_cursor[node]);          // broadcast across the 16 lanes
    int k = min(deg, CAP);

    float4 acc = make_float4(0.f, 0.f, 0.f, 0.f);
    const int* bkt = &g_bucket[node * CAP];

    #pragma unroll 4
    for (int i = 0; i < k; i++) {
        int s = __ldg(&bkt[i]);                // broadcast (single line per node)
        float rn = __ldg(&g_nsrc[s]);          // broadcast
        float4 v = __ldg(&feat[(long long)s * DVEC + q]);
        acc.x = fmaf(v.x, rn, acc.x);
        acc.y = fmaf(v.y, rn, acc.y);
        acc.z = fmaf(v.z, rn, acc.z);
        acc.w = fmaf(v.w, rn, acc.w);
    }

    // Slow path: edges that overflowed this node's bucket (expected: none).
    if (deg > CAP) {
        int ovfn = min(g_ovf_count, OVF_MAX);
        for (int j = 0; j < ovfn; j++) {
            if (g_ovf_dst[j] == node) {
                int s = g_ovf_src[j];
                float rn = __ldg(&g_nsrc[s]);
                float4 v = __ldg(&feat[(long long)s * DVEC + q]);
                acc.x = fmaf(v.x, rn, acc.x);
                acc.y = fmaf(v.y, rn, acc.y);
                acc.z = fmaf(v.z, rn, acc.z);
                acc.w = fmaf(v.w, rn, acc.w);
            }
        }
    }

    float nd = __ldg(&g_ndst[node]);
    acc.x *= nd; acc.y *= nd; acc.z *= nd; acc.w *= nd;
    out[(long long)node * DVEC + q] = acc;
}

extern "C" void kernel_launch(void* const* d_in, const int* in_sizes, int n_in,
                              void* d_out, int out_size) {
    const float4* feat = (const float4*)d_in[0];
    const int*    src  = (const int*)d_in[1];
    const int*    dst  = (const int*)d_in[2];
    float4*       out  = (float4*)d_out;

    int N = in_sizes[0] / DFEAT;   // 100000
    int E = in_sizes[1];           // 1000000

    // 1) zero scratch
    {
        int threads = 256;
        int blocks = (N + threads - 1) / threads;
        zero_kernel<<<blocks, threads>>>(N);
    }

    // 2) degree count + dst binning
    {
        int threads = 256;
        int blocks = (E + threads - 1) / threads;
        bin_kernel<<<blocks, threads>>>(src, dst, E);
    }

    // 3) per-node norms
    {
        int threads = 256;
        int blocks = (N + threads - 1) / threads;
        norm_kernel<<<blocks, threads>>>(N);
    }

    // 4) register-accumulated gather, single write per output element
    {
        long long total = (long long)N * DVEC;
        int threads = 256;
        int blocks = (int)((total + threads - 1) / threads);
        gather_kernel<<<blocks, threads>>>(feat, out, N);
    }
}